// round 4
// baseline (speedup 1.0000x reference)
#include <cuda_runtime.h>
#include <cuda_bf16.h>
#include <math.h>

#define NN   100000
#define EE   1600000
#define TOT  (EE + NN)
#define HIDD 128
#define EPSV 1e-5f
#define NB   98        // ceil(NN / 1024)

// packed fp32x2 helpers (sm_100a: FFMA2 only reachable via PTX)
#define PK2(d, x, y) asm("mov.b64 %0, {%1, %2};" : "=l"(d) : "f"(x), "f"(y))
#define UPK2(lo, hi, v) asm("mov.b64 {%0, %1}, %2;" : "=f"(lo), "=f"(hi) : "l"(v))
#define FMA2(c, a, b) asm("fma.rn.f32x2 %0, %1, %2, %0;" : "+l"(c) : "l"(a), "l"(b))

// ---------------- static scratch (no allocations allowed) ----------------
__device__ int   g_cnt[NN];
__device__ int   g_rowptr[NN + 1];
__device__ int   g_fill[NN];
__device__ float g_dinv[NN];
__device__ int   g_bsum[NB];
__device__ int   g_boff[NB];
__device__ __align__(16) int2  g_csr[TOT];   // {src, norm-as-bits} sorted by dst
__device__ __align__(16) float g_t[(size_t)NN * HIDD];    // GEMM output
__device__ __align__(16) float g_agg[(size_t)NN * HIDD];  // aggregated (+bias)
__device__ float g_stats[2 * HIDD];
__device__ float g_scale[HIDD];
__device__ float g_shift[HIDD];
__device__ float g_Wcat[HIDD * HIDD];        // [Wmu | Wls]

// ---------------- graph preprocessing ----------------
__global__ void k_init() {
    int i = blockIdx.x * blockDim.x + threadIdx.x;
    if (i < NN) g_cnt[i] = 1;  // self-loop
}

__global__ void k_count(const int* __restrict__ dst) {
    int i = blockIdx.x * blockDim.x + threadIdx.x;
    if (i < EE) atomicAdd(&g_cnt[dst[i]], 1);
}

__global__ void k_dinv() {
    int i = blockIdx.x * blockDim.x + threadIdx.x;
    if (i < NN) {
        g_dinv[i] = rsqrtf((float)g_cnt[i]);
        g_fill[i] = 0;
    }
}

__global__ void k_scan1() {
    __shared__ int sh[1024];
    int t = threadIdx.x;
    int i = blockIdx.x * 1024 + t;
    int v = (i < NN) ? g_cnt[i] : 0;
    sh[t] = v;
    __syncthreads();
    for (int off = 1; off < 1024; off <<= 1) {
        int add = (t >= off) ? sh[t - off] : 0;
        __syncthreads();
        sh[t] += add;
        __syncthreads();
    }
    if (i < NN) g_rowptr[i + 1] = sh[t];
    if (t == 1023) g_bsum[blockIdx.x] = sh[t];
}

__global__ void k_scan2() {
    int s = 0;
    for (int b = 0; b < NB; b++) { g_boff[b] = s; s += g_bsum[b]; }
}

__global__ void k_scan3() {
    int t = threadIdx.x;
    int i = blockIdx.x * 1024 + t;
    if (i < NN) g_rowptr[i + 1] += g_boff[blockIdx.x];
    if (i == 0) g_rowptr[0] = 0;
}

__global__ void k_fill(const int* __restrict__ src, const int* __restrict__ dst) {
    for (int e = blockIdx.x * blockDim.x + threadIdx.x; e < TOT;
         e += gridDim.x * blockDim.x) {
        int s, d; float w;
        if (e < EE) {
            s = src[e]; d = dst[e];
            w = g_dinv[s] * g_dinv[d];
        } else {
            s = d = e - EE;
            float di = g_dinv[s];
            w = di * di;
        }
        int pos = g_rowptr[d] + atomicAdd(&g_fill[d], 1);
        g_csr[pos] = make_int2(s, __float_as_int(w));
    }
}

// ---------------- SGEMM (packed f32x2): g_t[n,128] = A[n,K] @ B[K,128] ----
// SRC 0: A = x (K=256).  SRC 1: A = BNrelu(g_agg), B = W2.
// SRC 2: A = BNrelu(g_agg), B = g_Wcat.
// Block 0 also zeroes g_stats for the following gather.
template <int SRC>
__global__ void __launch_bounds__(256) k_sgemm(const float* __restrict__ Aext,
                                               const float* __restrict__ Bext) {
    const int K = (SRC == 0) ? 256 : 128;
    const float* A = (SRC == 0) ? Aext : g_agg;
    const float* B = (SRC == 2) ? g_Wcat : Bext;

    __shared__ float As[16][132];  // transposed: As[k][row]
    __shared__ float Bs[16][128];
    int row0 = blockIdx.x * 128;
    int tid = threadIdx.x;
    int tx = tid & 15;   // col group of 8
    int ty = tid >> 4;   // row group of 8

    if (blockIdx.x == 0) g_stats[tid] = 0.0f;

    // acc2[ip][j] = (C[2ip][j], C[2ip+1][j]) packed fp32x2
    unsigned long long acc2[4][8];
    unsigned long long zz;
    PK2(zz, 0.0f, 0.0f);
#pragma unroll
    for (int ip = 0; ip < 4; ip++)
#pragma unroll
        for (int j = 0; j < 8; j++) acc2[ip][j] = zz;

    for (int k0 = 0; k0 < K; k0 += 16) {
#pragma unroll
        for (int l = 0; l < 2; l++) {
            int f  = tid + l * 256;
            int r  = f >> 2;
            int c4 = f & 3;
            int gr = row0 + r;
            float4 v = make_float4(0.f, 0.f, 0.f, 0.f);
            if (gr < NN) {
                v = *(const float4*)(A + (size_t)gr * K + k0 + c4 * 4);
                if (SRC != 0) {
                    int c = k0 + c4 * 4;
                    v.x = fmaxf(fmaf(v.x, g_scale[c + 0], g_shift[c + 0]), 0.f);
                    v.y = fmaxf(fmaf(v.y, g_scale[c + 1], g_shift[c + 1]), 0.f);
                    v.z = fmaxf(fmaf(v.z, g_scale[c + 2], g_shift[c + 2]), 0.f);
                    v.w = fmaxf(fmaf(v.w, g_scale[c + 3], g_shift[c + 3]), 0.f);
                }
            }
            As[c4 * 4 + 0][r] = v.x;
            As[c4 * 4 + 1][r] = v.y;
            As[c4 * 4 + 2][r] = v.z;
            As[c4 * 4 + 3][r] = v.w;
        }
#pragma unroll
        for (int l = 0; l < 2; l++) {
            int f  = tid + l * 256;
            int kr = f >> 5;
            int c4 = f & 31;
            *(float4*)&Bs[kr][c4 * 4] =
                *(const float4*)(B + (size_t)(k0 + kr) * 128 + c4 * 4);
        }
        __syncthreads();
#pragma unroll
        for (int k = 0; k < 16; k++) {
            float4 a0 = *(float4*)&As[k][ty * 8];
            float4 a1 = *(float4*)&As[k][ty * 8 + 4];
            float4 b0 = *(float4*)&Bs[k][tx * 8];
            float4 b1 = *(float4*)&Bs[k][tx * 8 + 4];
            unsigned long long a2[4], bd[8];
            PK2(a2[0], a0.x, a0.y); PK2(a2[1], a0.z, a0.w);
            PK2(a2[2], a1.x, a1.y); PK2(a2[3], a1.z, a1.w);
            PK2(bd[0], b0.x, b0.x); PK2(bd[1], b0.y, b0.y);
            PK2(bd[2], b0.z, b0.z); PK2(bd[3], b0.w, b0.w);
            PK2(bd[4], b1.x, b1.x); PK2(bd[5], b1.y, b1.y);
            PK2(bd[6], b1.z, b1.z); PK2(bd[7], b1.w, b1.w);
#pragma unroll
            for (int ip = 0; ip < 4; ip++)
#pragma unroll
                for (int j = 0; j < 8; j++)
                    FMA2(acc2[ip][j], a2[ip], bd[j]);
        }
        __syncthreads();
    }
#pragma unroll
    for (int ip = 0; ip < 4; ip++) {
        float lo[8], hi[8];
#pragma unroll
        for (int j = 0; j < 8; j++) UPK2(lo[j], hi[j], acc2[ip][j]);
        int gr0 = row0 + ty * 8 + ip * 2;
        if (gr0 < NN) {
            *(float4*)(g_t + (size_t)gr0 * 128 + tx * 8) =
                make_float4(lo[0], lo[1], lo[2], lo[3]);
            *(float4*)(g_t + (size_t)gr0 * 128 + tx * 8 + 4) =
                make_float4(lo[4], lo[5], lo[6], lo[7]);
        }
        if (gr0 + 1 < NN) {
            *(float4*)(g_t + (size_t)(gr0 + 1) * 128 + tx * 8) =
                make_float4(hi[0], hi[1], hi[2], hi[3]);
            *(float4*)(g_t + (size_t)(gr0 + 1) * 128 + tx * 8 + 4) =
                make_float4(hi[4], hi[5], hi[6], hi[7]);
        }
    }
}

// ---------------- CSR gather: one warp per dst node ----------------
template <int EPI>
__global__ void __launch_bounds__(256) k_gather(const float* __restrict__ b0,
                                                const float* __restrict__ b1v,
                                                float* __restrict__ out) {
    __shared__ float s_part[8][256];
    int tid  = threadIdx.x;
    int lane = tid & 31;
    int wid  = tid >> 5;
    int warp = (blockIdx.x * 256 + tid) >> 5;
    int nw   = (gridDim.x * 256) >> 5;
    int c    = lane * 4;

    float rs0 = 0.f, rs1 = 0.f, rs2 = 0.f, rs3 = 0.f;
    float rq0 = 0.f, rq1 = 0.f, rq2 = 0.f, rq3 = 0.f;

    for (int d = warp; d < NN; d += nw) {
        int beg = g_rowptr[d];
        int end = g_rowptr[d + 1];
        float ax = 0.f, ay = 0.f, az = 0.f, aw = 0.f;
        for (int j = beg; j < end; j++) {
            int2  e = g_csr[j];
            float w = __int_as_float(e.y);
            float4 v = *(const float4*)(g_t + (size_t)e.x * 128 + c);
            ax = fmaf(v.x, w, ax);
            ay = fmaf(v.y, w, ay);
            az = fmaf(v.z, w, az);
            aw = fmaf(v.w, w, aw);
        }
        if (EPI == 0) {
            ax += b0[c + 0]; ay += b0[c + 1]; az += b0[c + 2]; aw += b0[c + 3];
            *(float4*)(g_agg + (size_t)d * 128 + c) = make_float4(ax, ay, az, aw);
            rs0 += ax; rs1 += ay; rs2 += az; rs3 += aw;
            rq0 = fmaf(ax, ax, rq0); rq1 = fmaf(ay, ay, rq1);
            rq2 = fmaf(az, az, rq2); rq3 = fmaf(aw, aw, rq3);
        } else {
            const float* bb = (lane < 16) ? b0 : b1v;      // bmu | bls
            int cc = (lane < 16) ? c : c - 64;
            ax += bb[cc + 0]; ay += bb[cc + 1]; az += bb[cc + 2]; aw += bb[cc + 3];
            float* dst = (lane < 16)
                ? out + (size_t)d * 64 + cc
                : out + (size_t)NN * 64 + (size_t)d * 64 + cc;
            *(float4*)dst = make_float4(ax, ay, az, aw);
        }
    }

    if (EPI == 0) {
        s_part[wid][c + 0] = rs0; s_part[wid][c + 1] = rs1;
        s_part[wid][c + 2] = rs2; s_part[wid][c + 3] = rs3;
        s_part[wid][128 + c + 0] = rq0; s_part[wid][128 + c + 1] = rq1;
        s_part[wid][128 + c + 2] = rq2; s_part[wid][128 + c + 3] = rq3;
        __syncthreads();
        float v = 0.f;
#pragma unroll
        for (int w = 0; w < 8; w++) v += s_part[w][tid];
        atomicAdd(&g_stats[tid], v);
    }
}

// ---------------- BN params from stats ----------------
__global__ void k_bnparams(const float* __restrict__ g, const float* __restrict__ bt) {
    int c = threadIdx.x;  // 128
    float m   = g_stats[c] * (1.0f / NN);
    float var = g_stats[128 + c] * (1.0f / NN) - m * m;
    float sc  = rsqrtf(var + EPSV) * g[c];
    g_scale[c] = sc;
    g_shift[c] = bt[c] - m * sc;
}

// ---------------- pack [Wmu | Wls] ----------------
__global__ void k_pack_w(const float* __restrict__ Wmu, const float* __restrict__ Wls) {
    int i = blockIdx.x * blockDim.x + threadIdx.x;
    if (i < 128 * 128) {
        int k = i >> 7, j = i & 127;
        g_Wcat[i] = (j < 64) ? Wmu[k * 64 + j] : Wls[k * 64 + (j - 64)];
    }
}

// ---------------- launch: kernel launches ONLY ----------------
extern "C" void kernel_launch(void* const* d_in, const int* in_sizes, int n_in,
                              void* d_out, int out_size) {
    const float* x   = (const float*)d_in[0];
    const float* W1  = (const float*)d_in[1];
    const float* b1  = (const float*)d_in[2];
    const float* g1  = (const float*)d_in[3];
    const float* bt1 = (const float*)d_in[4];
    const float* W2  = (const float*)d_in[5];
    const float* b2  = (const float*)d_in[6];
    const float* g2  = (const float*)d_in[7];
    const float* bt2 = (const float*)d_in[8];
    const float* Wmu = (const float*)d_in[9];
    const float* bmu = (const float*)d_in[10];
    const float* Wls = (const float*)d_in[11];
    const float* bls = (const float*)d_in[12];
    const int*   ei  = (const int*)d_in[13];
    const int* src = ei;
    const int* dst = ei + EE;
    float* out = (float*)d_out;

    const int GEMM_GRID = (NN + 127) / 128;

    // --- CSR build ---
    k_init<<<(NN + 255) / 256, 256>>>();
    k_count<<<(EE + 255) / 256, 256>>>(dst);
    k_dinv<<<(NN + 255) / 256, 256>>>();
    k_scan1<<<NB, 1024>>>();
    k_scan2<<<1, 1>>>();
    k_scan3<<<NB, 1024>>>();
    k_fill<<<4096, 256>>>(src, dst);

    // --- layer 1 ---
    k_sgemm<0><<<GEMM_GRID, 256>>>(x, W1);
    k_gather<0><<<2048, 256>>>(b1, nullptr, nullptr);
    k_bnparams<<<1, 128>>>(g1, bt1);

    // --- layer 2 ---
    k_sgemm<1><<<GEMM_GRID, 256>>>(nullptr, W2);
    k_gather<0><<<2048, 256>>>(b2, nullptr, nullptr);
    k_bnparams<<<1, 128>>>(g2, bt2);

    // --- layer 3 (fused mu/logstd) ---
    k_pack_w<<<64, 256>>>(Wmu, Wls);
    k_sgemm<2><<<GEMM_GRID, 256>>>(nullptr, nullptr);
    k_gather<1><<<2048, 256>>>(bmu, bls, out);
}

// round 5
// speedup vs baseline: 1.0806x; 1.0806x over previous
#include <cuda_runtime.h>
#include <cuda_bf16.h>
#include <math.h>

#define NN   100000
#define EE   1600000
#define TOT  (EE + NN)
#define HIDD 128
#define EPSV 1e-5f
#define NB   98        // ceil(NN / 1024)

// ---------------- static scratch (no allocations allowed) ----------------
__device__ int   g_cnt[NN];
__device__ int   g_rowptr[NN + 1];
__device__ int   g_fill[NN];
__device__ float g_dinv[NN];
__device__ int   g_bsum[NB];
__device__ int   g_boff[NB];
__device__ __align__(16) int2  g_csr[TOT];   // {src, norm-as-bits} sorted by dst
__device__ __align__(16) float g_t[(size_t)NN * HIDD];    // GEMM output
__device__ __align__(16) float g_agg[(size_t)NN * HIDD];  // aggregated (+bias)
__device__ float g_stats[2 * HIDD];
__device__ float g_scale[HIDD];
__device__ float g_shift[HIDD];
__device__ float g_Wcat[HIDD * HIDD];        // [Wmu | Wls]

// ---------------- tf32 helpers ----------------
__device__ __forceinline__ unsigned f2tf32(float f) {
    unsigned r;
    asm("cvt.rna.tf32.f32 %0, %1;" : "=r"(r) : "f"(f));
    return r;
}

#define MMA_TF32(c0, c1, c2, c3, a0, a1, a2, a3, b0, b1)                      \
    asm volatile(                                                             \
        "mma.sync.aligned.m16n8k8.row.col.f32.tf32.tf32.f32 "                 \
        "{%0,%1,%2,%3}, {%4,%5,%6,%7}, {%8,%9}, {%0,%1,%2,%3};"               \
        : "+f"(c0), "+f"(c1), "+f"(c2), "+f"(c3)                              \
        : "r"(a0), "r"(a1), "r"(a2), "r"(a3), "r"(b0), "r"(b1))

// ---------------- graph preprocessing ----------------
__global__ void k_init() {
    int i = blockIdx.x * blockDim.x + threadIdx.x;
    if (i < NN) g_cnt[i] = 1;  // self-loop
}

__global__ void k_count(const int* __restrict__ dst) {
    int i = blockIdx.x * blockDim.x + threadIdx.x;
    if (i < EE) atomicAdd(&g_cnt[dst[i]], 1);
}

__global__ void k_dinv() {
    int i = blockIdx.x * blockDim.x + threadIdx.x;
    if (i < NN) {
        g_dinv[i] = rsqrtf((float)g_cnt[i]);
        g_fill[i] = 0;
    }
}

__global__ void k_scan1() {
    __shared__ int sh[1024];
    int t = threadIdx.x;
    int i = blockIdx.x * 1024 + t;
    int v = (i < NN) ? g_cnt[i] : 0;
    sh[t] = v;
    __syncthreads();
    for (int off = 1; off < 1024; off <<= 1) {
        int add = (t >= off) ? sh[t - off] : 0;
        __syncthreads();
        sh[t] += add;
        __syncthreads();
    }
    if (i < NN) g_rowptr[i + 1] = sh[t];
    if (t == 1023) g_bsum[blockIdx.x] = sh[t];
}

__global__ void k_scan2() {
    int s = 0;
    for (int b = 0; b < NB; b++) { g_boff[b] = s; s += g_bsum[b]; }
}

__global__ void k_scan3() {
    int t = threadIdx.x;
    int i = blockIdx.x * 1024 + t;
    if (i < NN) g_rowptr[i + 1] += g_boff[blockIdx.x];
    if (i == 0) g_rowptr[0] = 0;
}

__global__ void k_fill(const int* __restrict__ src, const int* __restrict__ dst) {
    for (int e = blockIdx.x * blockDim.x + threadIdx.x; e < TOT;
         e += gridDim.x * blockDim.x) {
        int s, d; float w;
        if (e < EE) {
            s = src[e]; d = dst[e];
            w = g_dinv[s] * g_dinv[d];
        } else {
            s = d = e - EE;
            float di = g_dinv[s];
            w = di * di;
        }
        int pos = g_rowptr[d] + atomicAdd(&g_fill[d], 1);
        g_csr[pos] = make_int2(s, __float_as_int(w));
    }
}

// ---------------- 3xTF32 tensor-core GEMM ----------------
// g_t[n,128] = A[n,K] @ B[K,128].  Block tile 128(M) x 64(N); gridDim.x =
// 2*ceil(NN/128), col-block = bid & 1.  8 warps of 32x32 warp tiles.
// SRC 0: A = x (K=256).  SRC 1: A = BNrelu(g_agg), B = W2.
// SRC 2: A = BNrelu(g_agg), B = g_Wcat.  Block 0 zeroes g_stats.
template <int SRC>
__global__ void __launch_bounds__(256, 2) k_sgemm(const float* __restrict__ Aext,
                                                  const float* __restrict__ Bext) {
    const int K = (SRC == 0) ? 256 : 128;
    const float* A = (SRC == 0) ? Aext : g_agg;
    const float* B = (SRC == 2) ? g_Wcat : Bext;

    __shared__ float sA[128 * 36];  // As[m][k], stride 36 (banks: 4g+tig)
    __shared__ float sB[32 * 72];   // Bs[k][n], stride 72 (banks: 8tig+g)

    int bid  = blockIdx.x;
    int row0 = (bid >> 1) * 128;
    int col0 = (bid & 1) * 64;
    int tid  = threadIdx.x;
    int lane = tid & 31;
    int wid  = tid >> 5;
    int g    = lane >> 2;   // group id (0..7)
    int tig  = lane & 3;    // thread in group (0..3)
    int wm   = wid & 3;     // warp m (0..3) -> 32 rows
    int wn   = wid >> 2;    // warp n (0..1) -> 32 cols

    if (bid == 0) g_stats[tid] = 0.0f;

    float acc[2][4][4];     // [mi][nj][c0..c3]
#pragma unroll
    for (int mi = 0; mi < 2; mi++)
#pragma unroll
        for (int nj = 0; nj < 4; nj++)
#pragma unroll
            for (int q = 0; q < 4; q++) acc[mi][nj][q] = 0.0f;

    for (int k0 = 0; k0 < K; k0 += 32) {
        // --- load A tile 128x32 (BN+ReLU fused for SRC != 0) ---
#pragma unroll
        for (int l = 0; l < 4; l++) {
            int idx = tid + l * 256;        // 0..1023 float4 slots
            int r   = idx >> 3;             // 0..127
            int c4  = idx & 7;              // 0..7 (4 cols each)
            int gr  = row0 + r;
            float4 v = make_float4(0.f, 0.f, 0.f, 0.f);
            if (gr < NN) {
                v = *(const float4*)(A + (size_t)gr * K + k0 + c4 * 4);
                if (SRC != 0) {
                    int c = k0 + c4 * 4;
                    v.x = fmaxf(fmaf(v.x, g_scale[c + 0], g_shift[c + 0]), 0.f);
                    v.y = fmaxf(fmaf(v.y, g_scale[c + 1], g_shift[c + 1]), 0.f);
                    v.z = fmaxf(fmaf(v.z, g_scale[c + 2], g_shift[c + 2]), 0.f);
                    v.w = fmaxf(fmaf(v.w, g_scale[c + 3], g_shift[c + 3]), 0.f);
                }
            }
            *(float4*)(sA + r * 36 + c4 * 4) = v;
        }
        // --- load B tile 32x64 ---
#pragma unroll
        for (int l = 0; l < 2; l++) {
            int idx = tid * 2 + l;          // 0..511 float4 slots
            int r   = idx >> 4;             // 0..31
            int c4  = idx & 15;             // 0..15
            *(float4*)(sB + r * 72 + c4 * 4) =
                *(const float4*)(B + (size_t)(k0 + r) * 128 + col0 + c4 * 4);
        }
        __syncthreads();

#pragma unroll
        for (int kk = 0; kk < 4; kk++) {   // four k8 steps
            // A fragments (2 m16 tiles)
            unsigned ah[8], al[8];
#pragma unroll
            for (int mi = 0; mi < 2; mi++) {
                int rb = wm * 32 + mi * 16 + g;
                const float* pa = sA + rb * 36 + kk * 8 + tig;
                float o0 = pa[0];
                float o1 = pa[8 * 36];
                float o2 = pa[4];
                float o3 = pa[8 * 36 + 4];
                ah[mi*4+0] = f2tf32(o0); al[mi*4+0] = f2tf32(o0 - __uint_as_float(ah[mi*4+0]));
                ah[mi*4+1] = f2tf32(o1); al[mi*4+1] = f2tf32(o1 - __uint_as_float(ah[mi*4+1]));
                ah[mi*4+2] = f2tf32(o2); al[mi*4+2] = f2tf32(o2 - __uint_as_float(ah[mi*4+2]));
                ah[mi*4+3] = f2tf32(o3); al[mi*4+3] = f2tf32(o3 - __uint_as_float(ah[mi*4+3]));
            }
            // B fragments (4 n8 tiles)
            unsigned bh[8], bl[8];
#pragma unroll
            for (int nj = 0; nj < 4; nj++) {
                int cb = wn * 32 + nj * 8 + g;
                const float* pb = sB + (kk * 8 + tig) * 72 + cb;
                float o0 = pb[0];
                float o1 = pb[4 * 72];
                bh[nj*2+0] = f2tf32(o0); bl[nj*2+0] = f2tf32(o0 - __uint_as_float(bh[nj*2+0]));
                bh[nj*2+1] = f2tf32(o1); bl[nj*2+1] = f2tf32(o1 - __uint_as_float(bh[nj*2+1]));
            }
#pragma unroll
            for (int mi = 0; mi < 2; mi++)
#pragma unroll
                for (int nj = 0; nj < 4; nj++) {
                    float* c = acc[mi][nj];
                    MMA_TF32(c[0], c[1], c[2], c[3],
                             ah[mi*4], ah[mi*4+1], ah[mi*4+2], ah[mi*4+3],
                             bh[nj*2], bh[nj*2+1]);
                    MMA_TF32(c[0], c[1], c[2], c[3],
                             ah[mi*4], ah[mi*4+1], ah[mi*4+2], ah[mi*4+3],
                             bl[nj*2], bl[nj*2+1]);
                    MMA_TF32(c[0], c[1], c[2], c[3],
                             al[mi*4], al[mi*4+1], al[mi*4+2], al[mi*4+3],
                             bh[nj*2], bh[nj*2+1]);
                }
        }
        __syncthreads();
    }

    // --- epilogue: write C fragments ---
#pragma unroll
    for (int mi = 0; mi < 2; mi++) {
        int r1 = row0 + wm * 32 + mi * 16 + g;
        int r2 = r1 + 8;
#pragma unroll
        for (int nj = 0; nj < 4; nj++) {
            int cb = col0 + wn * 32 + nj * 8 + tig * 2;
            if (r1 < NN)
                *(float2*)(g_t + (size_t)r1 * 128 + cb) =
                    make_float2(acc[mi][nj][0], acc[mi][nj][1]);
            if (r2 < NN)
                *(float2*)(g_t + (size_t)r2 * 128 + cb) =
                    make_float2(acc[mi][nj][2], acc[mi][nj][3]);
        }
    }
}

// ---------------- CSR gather: one warp per dst node ----------------
template <int EPI>
__global__ void __launch_bounds__(256) k_gather(const float* __restrict__ b0,
                                                const float* __restrict__ b1v,
                                                float* __restrict__ out) {
    __shared__ float s_part[8][256];
    int tid  = threadIdx.x;
    int lane = tid & 31;
    int wid  = tid >> 5;
    int warp = (blockIdx.x * 256 + tid) >> 5;
    int nw   = (gridDim.x * 256) >> 5;
    int c    = lane * 4;

    float rs0 = 0.f, rs1 = 0.f, rs2 = 0.f, rs3 = 0.f;
    float rq0 = 0.f, rq1 = 0.f, rq2 = 0.f, rq3 = 0.f;

    for (int d = warp; d < NN; d += nw) {
        int beg = g_rowptr[d];
        int end = g_rowptr[d + 1];
        float ax = 0.f, ay = 0.f, az = 0.f, aw = 0.f;
        for (int j = beg; j < end; j++) {
            int2  e = g_csr[j];
            float w = __int_as_float(e.y);
            float4 v = *(const float4*)(g_t + (size_t)e.x * 128 + c);
            ax = fmaf(v.x, w, ax);
            ay = fmaf(v.y, w, ay);
            az = fmaf(v.z, w, az);
            aw = fmaf(v.w, w, aw);
        }
        if (EPI == 0) {
            ax += b0[c + 0]; ay += b0[c + 1]; az += b0[c + 2]; aw += b0[c + 3];
            *(float4*)(g_agg + (size_t)d * 128 + c) = make_float4(ax, ay, az, aw);
            rs0 += ax; rs1 += ay; rs2 += az; rs3 += aw;
            rq0 = fmaf(ax, ax, rq0); rq1 = fmaf(ay, ay, rq1);
            rq2 = fmaf(az, az, rq2); rq3 = fmaf(aw, aw, rq3);
        } else {
            const float* bb = (lane < 16) ? b0 : b1v;      // bmu | bls
            int cc = (lane < 16) ? c : c - 64;
            ax += bb[cc + 0]; ay += bb[cc + 1]; az += bb[cc + 2]; aw += bb[cc + 3];
            float* dst = (lane < 16)
                ? out + (size_t)d * 64 + cc
                : out + (size_t)NN * 64 + (size_t)d * 64 + cc;
            *(float4*)dst = make_float4(ax, ay, az, aw);
        }
    }

    if (EPI == 0) {
        s_part[wid][c + 0] = rs0; s_part[wid][c + 1] = rs1;
        s_part[wid][c + 2] = rs2; s_part[wid][c + 3] = rs3;
        s_part[wid][128 + c + 0] = rq0; s_part[wid][128 + c + 1] = rq1;
        s_part[wid][128 + c + 2] = rq2; s_part[wid][128 + c + 3] = rq3;
        __syncthreads();
        float v = 0.f;
#pragma unroll
        for (int w = 0; w < 8; w++) v += s_part[w][tid];
        atomicAdd(&g_stats[tid], v);
    }
}

// ---------------- BN params from stats ----------------
__global__ void k_bnparams(const float* __restrict__ g, const float* __restrict__ bt) {
    int c = threadIdx.x;  // 128
    float m   = g_stats[c] * (1.0f / NN);
    float var = g_stats[128 + c] * (1.0f / NN) - m * m;
    float sc  = rsqrtf(var + EPSV) * g[c];
    g_scale[c] = sc;
    g_shift[c] = bt[c] - m * sc;
}

// ---------------- pack [Wmu | Wls] ----------------
__global__ void k_pack_w(const float* __restrict__ Wmu, const float* __restrict__ Wls) {
    int i = blockIdx.x * blockDim.x + threadIdx.x;
    if (i < 128 * 128) {
        int k = i >> 7, j = i & 127;
        g_Wcat[i] = (j < 64) ? Wmu[k * 64 + j] : Wls[k * 64 + (j - 64)];
    }
}

// ---------------- launch: kernel launches ONLY ----------------
extern "C" void kernel_launch(void* const* d_in, const int* in_sizes, int n_in,
                              void* d_out, int out_size) {
    const float* x   = (const float*)d_in[0];
    const float* W1  = (const float*)d_in[1];
    const float* b1  = (const float*)d_in[2];
    const float* g1  = (const float*)d_in[3];
    const float* bt1 = (const float*)d_in[4];
    const float* W2  = (const float*)d_in[5];
    const float* b2  = (const float*)d_in[6];
    const float* g2  = (const float*)d_in[7];
    const float* bt2 = (const float*)d_in[8];
    const float* Wmu = (const float*)d_in[9];
    const float* bmu = (const float*)d_in[10];
    const float* Wls = (const float*)d_in[11];
    const float* bls = (const float*)d_in[12];
    const int*   ei  = (const int*)d_in[13];
    const int* src = ei;
    const int* dst = ei + EE;
    float* out = (float*)d_out;

    const int GEMM_GRID = 2 * ((NN + 127) / 128);

    // --- CSR build ---
    k_init<<<(NN + 255) / 256, 256>>>();
    k_count<<<(EE + 255) / 256, 256>>>(dst);
    k_dinv<<<(NN + 255) / 256, 256>>>();
    k_scan1<<<NB, 1024>>>();
    k_scan2<<<1, 1>>>();
    k_scan3<<<NB, 1024>>>();
    k_fill<<<4096, 256>>>(src, dst);

    // --- layer 1 ---
    k_sgemm<0><<<GEMM_GRID, 256>>>(x, W1);
    k_gather<0><<<2048, 256>>>(b1, nullptr, nullptr);
    k_bnparams<<<1, 128>>>(g1, bt1);

    // --- layer 2 ---
    k_sgemm<1><<<GEMM_GRID, 256>>>(nullptr, W2);
    k_gather<0><<<2048, 256>>>(b2, nullptr, nullptr);
    k_bnparams<<<1, 128>>>(g2, bt2);

    // --- layer 3 (fused mu/logstd) ---
    k_pack_w<<<64, 256>>>(Wmu, Wls);
    k_sgemm<2><<<GEMM_GRID, 256>>>(nullptr, nullptr);
    k_gather<1><<<2048, 256>>>(bmu, bls, out);
}